// round 5
// baseline (speedup 1.0000x reference)
#include <cuda_runtime.h>
#include <cstdint>

// ---------------------------------------------------------------------------
// VQ-VAE VectorQuantizer, GB300 sm_103 (legacy-PTX toolchain: no tcgen05).
// R5: warp-level mma.sync tf32 computes approximate scores -2*z.e + ||e||^2;
// per-pixel top-2 tracked in registers; pixels with gap < EPS re-resolved by
// a bit-exact kernel reproducing the reference fp32 chains.
// ---------------------------------------------------------------------------

constexpr int CC     = 64;
constexpr int CHW    = 4096;
constexpr int NPIX   = 65536;
constexpr int KCB    = 1024;
constexpr int TILE   = 128;            // pixels per CTA
constexpr int NCTA   = NPIX / TILE;    // 512
constexpr int NTHR   = 256;            // 8 warps
constexpr int CHUNK  = 128;            // codes staged per smem chunk
constexpr int NCHUNK = KCB / CHUNK;    // 8

constexpr int Q_ELEMS = 4194304;
constexpr int LOSS0   = Q_ELEMS;
constexpr int LOSS1   = Q_ELEMS + 1;
constexpr int IDX0    = Q_ELEMS + 2;

constexpr float EPS = 1.0e-4f;         // tf32 score err ~2.4e-6 RMS

constexpr int RSZ = 132;               // zs row stride (floats)
constexpr int RSB = 68;                // bs row stride (floats) — conflict-free ldsm
constexpr int SM_ZS = 0;                               // 64 x 132 x 4  = 33792
constexpr int SM_BS = 64 * RSZ * 4;                    // 128 x 68 x 4  = 34816
constexpr int SM_E2 = SM_BS + CHUNK * RSB * 4;         // 512
constexpr int SMEM_SZ = SM_E2 + 512 + 256;             // ~69.9 KB

__device__ int   g_cnt;
__device__ int   g_list[NPIX];
__device__ float g_part[256];

// ---- PTX helpers -----------------------------------------------------------
__device__ __forceinline__ uint32_t smem_u32(const void* p) {
    uint32_t a;
    asm("{ .reg .u64 t; cvta.to.shared.u64 t, %1; cvt.u32.u64 %0, t; }"
        : "=r"(a) : "l"(p));
    return a;
}
__device__ __forceinline__ uint32_t f2tf32(float f) {
    uint32_t u;
    asm("cvt.rna.tf32.f32 %0, %1;" : "=r"(u) : "f"(f));
    return u;
}
__device__ __forceinline__ void ldsm4(uint32_t& a0, uint32_t& a1,
                                      uint32_t& a2, uint32_t& a3, uint32_t addr) {
    asm volatile("ldmatrix.sync.aligned.m8n8.x4.shared.b16 {%0,%1,%2,%3}, [%4];"
                 : "=r"(a0), "=r"(a1), "=r"(a2), "=r"(a3) : "r"(addr));
}
__device__ __forceinline__ void mma8(float& c0, float& c1, float& c2, float& c3,
                                     uint32_t a0, uint32_t a1, uint32_t a2, uint32_t a3,
                                     uint32_t b0, uint32_t b1) {
    asm volatile("mma.sync.aligned.m16n8k8.row.col.f32.tf32.tf32.f32 "
                 "{%0,%1,%2,%3}, {%4,%5,%6,%7}, {%8,%9}, {%0,%1,%2,%3};"
                 : "+f"(c0), "+f"(c1), "+f"(c2), "+f"(c3)
                 : "r"(a0), "r"(a1), "r"(a2), "r"(a3), "r"(b0), "r"(b1));
}

// ---- K1: tensor approximate argmin + flagging ------------------------------
__global__ void __launch_bounds__(NTHR, 3)
vq_mma(const float* __restrict__ z, const float* __restrict__ emb,
       float* __restrict__ out) {
    extern __shared__ char smem[];
    float* zs  = reinterpret_cast<float*>(smem + SM_ZS);   // [64][132]
    float* bs  = reinterpret_cast<float*>(smem + SM_BS);   // [128][68] (tf32 bits)
    float* e2s = reinterpret_cast<float*>(smem + SM_E2);   // [128]

    const int tid = threadIdx.x, warp = tid >> 5, lane = tid & 31;
    const int pbase = blockIdx.x * TILE;
    const int bb = pbase >> 12, hw0 = pbase & 4095;
    const float* zb = z + (size_t)bb * (CC * CHW) + hw0;

    // ---- stage z tile [c][pix] (coalesced) --------------------------------
    #pragma unroll
    for (int i = 0; i < 8; i++) {
        int q = tid + i * NTHR;             // 0..2047 float4
        int c = q >> 5, p4 = (q & 31) * 4;
        float4 v = *reinterpret_cast<const float4*>(zb + c * CHW + p4);
        *reinterpret_cast<float4*>(zs + c * RSZ + p4) = v;
    }
    __syncthreads();

    // ---- preload B fragments (z pixels), converted to tf32 ----------------
    // b0 = z[ch = kt*8 + lane%4][pix = wp + nt*8 + lane/4], b1 = ch+4
    const int wp = warp * 16;
    uint32_t bz[32];
    #pragma unroll
    for (int nt = 0; nt < 2; nt++)
        #pragma unroll
        for (int kt = 0; kt < 8; kt++) {
            int px = wp + nt * 8 + (lane >> 2);
            int c0 = kt * 8 + (lane & 3);
            bz[(nt * 8 + kt) * 2 + 0] = f2tf32(zs[(c0    ) * RSZ + px]);
            bz[(nt * 8 + kt) * 2 + 1] = f2tf32(zs[(c0 + 4) * RSZ + px]);
        }

    float B1[4] = {3.4e38f, 3.4e38f, 3.4e38f, 3.4e38f};
    float B2[4] = {3.4e38f, 3.4e38f, 3.4e38f, 3.4e38f};
    int   K1[4] = {0, 0, 0, 0};

    const uint32_t bs_u = smem_u32(bs);
    const uint32_t ld_fixed = ((lane & 15) * RSB + ((lane & 16) >> 2)) * 4;

    for (int ch = 0; ch < NCHUNK; ch++) {
        __syncthreads();                     // prior chunk fully consumed
        // ---- stage codebook chunk, converting to tf32 ---------------------
        const float4* eb = reinterpret_cast<const float4*>(emb + ch * CHUNK * CC);
        #pragma unroll
        for (int i = 0; i < 8; i++) {
            int q = tid + i * NTHR;          // 0..2047 float4
            int code = q >> 4, c4 = (q & 15) * 4;
            float4 v = __ldg(eb + q);
            uint4 t;
            t.x = f2tf32(v.x); t.y = f2tf32(v.y);
            t.z = f2tf32(v.z); t.w = f2tf32(v.w);
            *reinterpret_cast<uint4*>(bs + code * RSB + c4) = t;
        }
        __syncthreads();
        if (tid < CHUNK) {                   // ||e||^2 from tf32 values
            float s = 0.f;
            const float* r = bs + tid * RSB;
            #pragma unroll
            for (int c = 0; c < CC; c++) s += r[c] * r[c];
            e2s[tid] = s;
        }
        __syncthreads();

        // ---- 8 m-tiles of 16 codes --------------------------------------
        for (int m0 = 0; m0 < CHUNK; m0 += 16) {
            float C0[4] = {0.f, 0.f, 0.f, 0.f};
            float C1[4] = {0.f, 0.f, 0.f, 0.f};
            uint32_t mrow = bs_u + m0 * (RSB * 4) + ld_fixed;
            #pragma unroll
            for (int kt = 0; kt < 8; kt++) {
                uint32_t a0, a1, a2, a3;
                ldsm4(a0, a1, a2, a3, mrow + kt * 32);
                mma8(C0[0], C0[1], C0[2], C0[3], a0, a1, a2, a3,
                     bz[(0 * 8 + kt) * 2], bz[(0 * 8 + kt) * 2 + 1]);
                mma8(C1[0], C1[1], C1[2], C1[3], a0, a1, a2, a3,
                     bz[(1 * 8 + kt) * 2], bz[(1 * 8 + kt) * 2 + 1]);
            }
            const float e2lo = e2s[m0 + (lane >> 2)];
            const float e2hi = e2s[m0 + 8 + (lane >> 2)];
            const int klo = ch * CHUNK + m0 + (lane >> 2);
            const int khi = klo + 8;
            // slot = nt*2 + colbit ; update klo before khi (k ascending)
            #pragma unroll
            for (int nt = 0; nt < 2; nt++) {
                float* C = nt ? C1 : C0;
                #pragma unroll
                for (int cb = 0; cb < 2; cb++) {
                    int s = nt * 2 + cb;
                    float slo = __fmaf_rn(-2.f, C[cb], e2lo);
                    float shi = __fmaf_rn(-2.f, C[2 + cb], e2hi);
                    if (slo < B1[s]) { B2[s] = B1[s]; B1[s] = slo; K1[s] = klo; }
                    else if (slo < B2[s]) B2[s] = slo;
                    if (shi < B1[s]) { B2[s] = B1[s]; B1[s] = shi; K1[s] = khi; }
                    else if (shi < B2[s]) B2[s] = shi;
                }
            }
        }
    }

    // ---- merge top-2 across the 8 lanes sharing each pixel column ---------
    #pragma unroll
    for (int s = 0; s < 4; s++) {
        float b1 = B1[s], b2 = B2[s]; int k1 = K1[s];
        #pragma unroll
        for (int off = 4; off <= 16; off <<= 1) {
            float ob1 = __shfl_xor_sync(0xffffffffu, b1, off);
            float ob2 = __shfl_xor_sync(0xffffffffu, b2, off);
            int   ok1 = __shfl_xor_sync(0xffffffffu, k1, off);
            if (ob1 < b1 || (ob1 == b1 && ok1 < k1)) {
                b2 = fminf(b1, ob2); b1 = ob1; k1 = ok1;
            } else {
                b2 = fminf(b2, ob1);
            }
        }
        B1[s] = b1; B2[s] = b2; K1[s] = k1;
    }
    if (lane < 4) {
        const int base = pbase + wp;
        const int pixs[4] = { base + 2 * lane,     base + 2 * lane + 1,
                              base + 8 + 2 * lane, base + 8 + 2 * lane + 1 };
        #pragma unroll
        for (int s = 0; s < 4; s++) {
            out[IDX0 + pixs[s]] = (float)K1[s];
            if (B2[s] - B1[s] < EPS) {
                int pos = atomicAdd(&g_cnt, 1);
                g_list[pos] = pixs[s];
            }
        }
    }
}

// ---- K2: bit-exact resolve of flagged pixels -------------------------------
__global__ void __launch_bounds__(256)
vq_exact(const float* __restrict__ z, const float* __restrict__ emb,
         float* __restrict__ out) {
    __shared__ float zs[CC];
    __shared__ float bvs[8];
    __shared__ int   bks[8];
    const int tid = threadIdx.x, wid = tid >> 5, lid = tid & 31;
    const int n = g_cnt;

    for (int w = blockIdx.x; w < n; w += gridDim.x) {
        const int p = g_list[w];
        const int b = p >> 12, hw = p & 4095;
        if (tid < CC) zs[tid] = z[(size_t)b * (CC * CHW) + tid * CHW + hw];
        __syncthreads();

        float zz = 0.f;
        #pragma unroll
        for (int c = 0; c < CC; c++) zz = __fadd_rn(zz, __fmul_rn(zs[c], zs[c]));

        float bv = 3.4e38f; int bk = 0;
        #pragma unroll
        for (int j = 0; j < 4; j++) {
            const int k = tid * 4 + j;
            const float4* er = reinterpret_cast<const float4*>(emb + (size_t)k * CC);
            float dot = 0.f, e2 = 0.f;
            #pragma unroll
            for (int i = 0; i < 16; i++) {
                float4 e4 = __ldg(er + i);
                float ev[4] = {e4.x, e4.y, e4.z, e4.w};
                #pragma unroll
                for (int q = 0; q < 4; q++) {
                    int c = 4 * i + q;
                    dot = __fmaf_rn(zs[c], ev[q], dot);
                    e2  = __fadd_rn(e2, __fmul_rn(ev[q], ev[q]));
                }
            }
            float d = __fsub_rn(__fadd_rn(zz, e2), __fmul_rn(2.0f, dot));
            if (d < bv) { bv = d; bk = k; }
        }
        #pragma unroll
        for (int o = 16; o; o >>= 1) {
            float ov = __shfl_xor_sync(0xffffffffu, bv, o);
            int   ok = __shfl_xor_sync(0xffffffffu, bk, o);
            if (ov < bv || (ov == bv && ok < bk)) { bv = ov; bk = ok; }
        }
        if (lid == 0) { bvs[wid] = bv; bks[wid] = bk; }
        __syncthreads();
        if (tid == 0) {
            float fv = bvs[0]; int fk = bks[0];
            #pragma unroll
            for (int i = 1; i < 8; i++)
                if (bvs[i] < fv || (bvs[i] == fv && bks[i] < fk)) { fv = bvs[i]; fk = bks[i]; }
            out[IDX0 + p] = (float)fk;
        }
        __syncthreads();
    }
}

// ---- K3: emit q + loss partials from final idx -----------------------------
__global__ void __launch_bounds__(256)
vq_emit(const float* __restrict__ z, const float* __restrict__ emb,
        float* __restrict__ out) {
    __shared__ float reds[8];
    const int p = blockIdx.x * 256 + threadIdx.x;
    const int b = p >> 12, hw = p & 4095;
    const int k = (int)out[IDX0 + p];
    const float4* er = reinterpret_cast<const float4*>(emb + (size_t)k * CC);
    const float* zp = z + (size_t)b * (CC * CHW) + hw;
    float* qp = out + (size_t)b * (CC * CHW) + hw;

    float sumsq = 0.f;
    #pragma unroll
    for (int i = 0; i < 16; i++) {
        float4 e4 = __ldg(er + i);
        float ev[4] = {e4.x, e4.y, e4.z, e4.w};
        #pragma unroll
        for (int j = 0; j < 4; j++) {
            int c = 4 * i + j;
            float zv = zp[c * CHW];
            float dd = __fsub_rn(ev[j], zv);
            sumsq = __fadd_rn(sumsq, __fmul_rn(dd, dd));
            qp[c * CHW] = __fadd_rn(zv, dd);          // fl(z + fl(e - z))
        }
    }
    #pragma unroll
    for (int o = 16; o; o >>= 1)
        sumsq += __shfl_xor_sync(0xffffffffu, sumsq, o);
    if ((threadIdx.x & 31) == 0) reds[threadIdx.x >> 5] = sumsq;
    __syncthreads();
    if (threadIdx.x == 0) {
        float s = 0.f;
        #pragma unroll
        for (int w = 0; w < 8; w++) s += reds[w];
        g_part[blockIdx.x] = s;
    }
}

// ---- K4: finalize losses, reset worklist for next graph replay -------------
__global__ void vq_fin(float* __restrict__ out) {
    float s = 0.f;
    for (int i = 0; i < 256; i++) s += g_part[i];
    float loss = s * (1.0f / (float)Q_ELEMS);
    out[LOSS0] = loss;
    out[LOSS1] = loss;
    g_cnt = 0;
}

extern "C" void kernel_launch(void* const* d_in, const int* in_sizes, int n_in,
                              void* d_out, int out_size) {
    const float* z   = (const float*)d_in[0];
    const float* emb = (const float*)d_in[1];
    float* out = (float*)d_out;

    static bool attr_set = false;
    if (!attr_set) {
        cudaFuncSetAttribute(vq_mma, cudaFuncAttributeMaxDynamicSharedMemorySize, SMEM_SZ);
        attr_set = true;
    }
    vq_mma<<<NCTA, NTHR, SMEM_SZ>>>(z, emb, out);
    vq_exact<<<512, 256>>>(z, emb, out);
    vq_emit<<<NPIX / 256, 256>>>(z, emb, out);
    vq_fin<<<1, 1>>>(out);
}

// round 9
// speedup vs baseline: 1.1301x; 1.1301x over previous
#include <cuda_runtime.h>
#include <cuda_fp16.h>
#include <cstdint>

// ---------------------------------------------------------------------------
// VQ-VAE VectorQuantizer, GB300 sm_103 (legacy-PTX toolchain).
// R7 = R6 resubmit (R6 bench was an infra failure, no signal).
// fp16 mma.sync m16n8k16 (f32 accum) scores -2*z.e + ||e||^2; per-pixel
// top-2 tracked; pixels with approx gap < EPS re-resolved bit-exactly.
// ---------------------------------------------------------------------------

constexpr int CC     = 64;
constexpr int CHW    = 4096;
constexpr int NPIX   = 65536;
constexpr int KCB    = 1024;
constexpr int TILE   = 128;            // pixels per CTA
constexpr int NCTA   = NPIX / TILE;    // 512
constexpr int NTHR   = 256;            // 8 warps
constexpr int CHUNK  = 128;            // codes per smem chunk
constexpr int NCHUNK = KCB / CHUNK;    // 8

constexpr int Q_ELEMS = 4194304;
constexpr int LOSS0   = Q_ELEMS;
constexpr int LOSS1   = Q_ELEMS + 1;
constexpr int IDX0    = Q_ELEMS + 2;

constexpr float EPS = 1.0e-4f;         // fp16 score err ~2.6e-6 RMS (38 sigma)

constexpr int RSZ  = 132;              // zs row stride (floats)
constexpr int RSB  = 72;               // bs row stride (fp16) = 144B, 16B-aligned
constexpr int SM_ZS = 0;                               // 64*132*4 = 33792
constexpr int SM_BS = 64 * RSZ * 4;                    // 128*144  = 18432
constexpr int SM_E2 = SM_BS + CHUNK * RSB * 2;         // 512
constexpr int SMEM_SZ = SM_E2 + 512 + 64;              // ~52.8 KB

__device__ int   g_cnt;
__device__ int   g_list[NPIX];
__device__ float g_part[256];

// ---- PTX helpers -----------------------------------------------------------
__device__ __forceinline__ uint32_t smem_u32(const void* p) {
    uint32_t a;
    asm("{ .reg .u64 t; cvta.to.shared.u64 t, %1; cvt.u32.u64 %0, t; }"
        : "=r"(a) : "l"(p));
    return a;
}
__device__ __forceinline__ uint32_t packh2(float lo, float hi) {
    __half2 h = __floats2half2_rn(lo, hi);
    return *reinterpret_cast<uint32_t*>(&h);
}
__device__ __forceinline__ void ldsm4(uint32_t& a0, uint32_t& a1,
                                      uint32_t& a2, uint32_t& a3, uint32_t addr) {
    asm volatile("ldmatrix.sync.aligned.m8n8.x4.shared.b16 {%0,%1,%2,%3}, [%4];"
                 : "=r"(a0), "=r"(a1), "=r"(a2), "=r"(a3) : "r"(addr));
}
__device__ __forceinline__ void mma16(float& c0, float& c1, float& c2, float& c3,
                                      uint32_t a0, uint32_t a1, uint32_t a2, uint32_t a3,
                                      uint32_t b0, uint32_t b1) {
    asm volatile("mma.sync.aligned.m16n8k16.row.col.f32.f16.f16.f32 "
                 "{%0,%1,%2,%3}, {%4,%5,%6,%7}, {%8,%9}, {%0,%1,%2,%3};"
                 : "+f"(c0), "+f"(c1), "+f"(c2), "+f"(c3)
                 : "r"(a0), "r"(a1), "r"(a2), "r"(a3), "r"(b0), "r"(b1));
}

// ---- K1: fp16 tensor approximate argmin + flagging -------------------------
__global__ void __launch_bounds__(NTHR)
vq_mma(const float* __restrict__ z, const float* __restrict__ emb,
       float* __restrict__ out) {
    extern __shared__ char smem[];
    float*  zs  = reinterpret_cast<float*>(smem + SM_ZS);    // [64][132] f32
    __half* bs  = reinterpret_cast<__half*>(smem + SM_BS);   // [128][72] f16
    float*  e2s = reinterpret_cast<float*>(smem + SM_E2);    // [128]

    const int tid = threadIdx.x, warp = tid >> 5, lane = tid & 31;
    const int pbase = blockIdx.x * TILE;
    const int bb = pbase >> 12, hw0 = pbase & 4095;
    const float* zb = z + (size_t)bb * (CC * CHW) + hw0;

    // ---- stage z tile [c][pix] (coalesced) --------------------------------
    #pragma unroll
    for (int i = 0; i < 8; i++) {
        int q = tid + i * NTHR;
        int c = q >> 5, p4 = (q & 31) * 4;
        float4 v = *reinterpret_cast<const float4*>(zb + c * CHW + p4);
        *reinterpret_cast<float4*>(zs + c * RSZ + p4) = v;
    }
    __syncthreads();

    // ---- preload fp16 B fragments (z pixels) ------------------------------
    // per (nt, kt): b0 = {z[c0], z[c0+1]}, b1 = {z[c0+8], z[c0+9]} at px
    const int wp = warp * 16;
    uint32_t bz[16];
    #pragma unroll
    for (int nt = 0; nt < 2; nt++)
        #pragma unroll
        for (int kt = 0; kt < 4; kt++) {
            int px = wp + nt * 8 + (lane >> 2);
            int c0 = kt * 16 + (lane & 3) * 2;
            bz[(nt * 4 + kt) * 2 + 0] = packh2(zs[(c0    ) * RSZ + px],
                                               zs[(c0 + 1) * RSZ + px]);
            bz[(nt * 4 + kt) * 2 + 1] = packh2(zs[(c0 + 8) * RSZ + px],
                                               zs[(c0 + 9) * RSZ + px]);
        }

    float B1[4] = {3.4e38f, 3.4e38f, 3.4e38f, 3.4e38f};
    float B2[4] = {3.4e38f, 3.4e38f, 3.4e38f, 3.4e38f};
    int   K1[4] = {0, 0, 0, 0};

    const uint32_t bs_u = smem_u32(bs);
    // ldmatrix lane ptr: row = m0 + (lane&15), 16B-half = lane>>4
    const uint32_t ld_fixed = (lane & 15) * (RSB * 2) + (lane >> 4) * 16;

    for (int ch = 0; ch < NCHUNK; ch++) {
        __syncthreads();                     // prior chunk fully consumed
        // ---- stage codebook chunk as fp16 + fold in ||e||^2 ---------------
        const float4* eb = reinterpret_cast<const float4*>(emb + ch * CHUNK * CC);
        #pragma unroll
        for (int i = 0; i < 8; i++) {
            int q = tid + i * NTHR;          // 0..2047 float4
            int code = q >> 4, c4 = (q & 15) * 4;
            float4 v = __ldg(eb + q);
            uint2 h;
            h.x = packh2(v.x, v.y);
            h.y = packh2(v.z, v.w);
            *reinterpret_cast<uint2*>(bs + code * RSB + c4) = h;
            float ps = v.x * v.x + v.y * v.y + v.z * v.z + v.w * v.w;
            ps += __shfl_xor_sync(0xffffffffu, ps, 1);
            ps += __shfl_xor_sync(0xffffffffu, ps, 2);
            ps += __shfl_xor_sync(0xffffffffu, ps, 4);
            ps += __shfl_xor_sync(0xffffffffu, ps, 8);
            if ((lane & 15) == 0) e2s[code] = ps;   // 16 lanes per code
        }
        __syncthreads();

        // ---- 8 m-tiles of 16 codes ----------------------------------------
        for (int m0 = 0; m0 < CHUNK; m0 += 16) {
            float C0[4] = {0.f, 0.f, 0.f, 0.f};
            float C1[4] = {0.f, 0.f, 0.f, 0.f};
            uint32_t mrow = bs_u + m0 * (RSB * 2) + ld_fixed;
            #pragma unroll
            for (int kt = 0; kt < 4; kt++) {
                uint32_t a0, a1, a2, a3;
                ldsm4(a0, a1, a2, a3, mrow + kt * 32);
                mma16(C0[0], C0[1], C0[2], C0[3], a0, a1, a2, a3,
                      bz[(0 * 4 + kt) * 2], bz[(0 * 4 + kt) * 2 + 1]);
                mma16(C1[0], C1[1], C1[2], C1[3], a0, a1, a2, a3,
                      bz[(1 * 4 + kt) * 2], bz[(1 * 4 + kt) * 2 + 1]);
            }
            const float e2lo = e2s[m0 + (lane >> 2)];
            const float e2hi = e2s[m0 + 8 + (lane >> 2)];
            const int klo = ch * CHUNK + m0 + (lane >> 2);
            const int khi = klo + 8;
            #pragma unroll
            for (int nt = 0; nt < 2; nt++) {
                float* C = nt ? C1 : C0;
                #pragma unroll
                for (int cb = 0; cb < 2; cb++) {
                    int s = nt * 2 + cb;
                    float slo = __fmaf_rn(-2.f, C[cb], e2lo);
                    float shi = __fmaf_rn(-2.f, C[2 + cb], e2hi);
                    if (slo < B1[s]) { B2[s] = B1[s]; B1[s] = slo; K1[s] = klo; }
                    else if (slo < B2[s]) B2[s] = slo;
                    if (shi < B1[s]) { B2[s] = B1[s]; B1[s] = shi; K1[s] = khi; }
                    else if (shi < B2[s]) B2[s] = shi;
                }
            }
        }
    }

    // ---- merge top-2 across the 8 lanes sharing each pixel column ---------
    #pragma unroll
    for (int s = 0; s < 4; s++) {
        float b1 = B1[s], b2 = B2[s]; int k1 = K1[s];
        #pragma unroll
        for (int off = 4; off <= 16; off <<= 1) {
            float ob1 = __shfl_xor_sync(0xffffffffu, b1, off);
            float ob2 = __shfl_xor_sync(0xffffffffu, b2, off);
            int   ok1 = __shfl_xor_sync(0xffffffffu, k1, off);
            if (ob1 < b1 || (ob1 == b1 && ok1 < k1)) {
                b2 = fminf(b1, ob2); b1 = ob1; k1 = ok1;
            } else {
                b2 = fminf(b2, ob1);
            }
        }
        B1[s] = b1; B2[s] = b2; K1[s] = k1;
    }
    if (lane < 4) {
        const int base = pbase + wp;
        const int pixs[4] = { base + 2 * lane,     base + 2 * lane + 1,
                              base + 8 + 2 * lane, base + 8 + 2 * lane + 1 };
        #pragma unroll
        for (int s = 0; s < 4; s++) {
            out[IDX0 + pixs[s]] = (float)K1[s];
            if (B2[s] - B1[s] < EPS) {
                int pos = atomicAdd(&g_cnt, 1);
                g_list[pos] = pixs[s];
            }
        }
    }
}

// ---- K2: bit-exact resolve of flagged pixels -------------------------------
__global__ void __launch_bounds__(256)
vq_exact(const float* __restrict__ z, const float* __restrict__ emb,
         float* __restrict__ out) {
    __shared__ float zs[CC];
    __shared__ float bvs[8];
    __shared__ int   bks[8];
    const int tid = threadIdx.x, wid = tid >> 5, lid = tid & 31;
    const int n = g_cnt;

    for (int w = blockIdx.x; w < n; w += gridDim.x) {
        const int p = g_list[w];
        const int b = p >> 12, hw = p & 4095;
        if (tid < CC) zs[tid] = z[(size_t)b * (CC * CHW) + tid * CHW + hw];
        __syncthreads();

        float zz = 0.f;
        #pragma unroll
        for (int c = 0; c < CC; c++) zz = __fadd_rn(zz, __fmul_rn(zs[c], zs[c]));

        float bv = 3.4e38f; int bk = 0;
        #pragma unroll
        for (int j = 0; j < 4; j++) {
            const int k = tid * 4 + j;
            const float4* er = reinterpret_cast<const float4*>(emb + (size_t)k * CC);
            float dot = 0.f, e2 = 0.f;
            #pragma unroll
            for (int i = 0; i < 16; i++) {
                float4 e4 = __ldg(er + i);
                float ev[4] = {e4.x, e4.y, e4.z, e4.w};
                #pragma unroll
                for (int q = 0; q < 4; q++) {
                    int c = 4 * i + q;
                    dot = __fmaf_rn(zs[c], ev[q], dot);
                    e2  = __fadd_rn(e2, __fmul_rn(ev[q], ev[q]));
                }
            }
            float d = __fsub_rn(__fadd_rn(zz, e2), __fmul_rn(2.0f, dot));
            if (d < bv) { bv = d; bk = k; }
        }
        #pragma unroll
        for (int o = 16; o; o >>= 1) {
            float ov = __shfl_xor_sync(0xffffffffu, bv, o);
            int   ok = __shfl_xor_sync(0xffffffffu, bk, o);
            if (ov < bv || (ov == bv && ok < bk)) { bv = ov; bk = ok; }
        }
        if (lid == 0) { bvs[wid] = bv; bks[wid] = bk; }
        __syncthreads();
        if (tid == 0) {
            float fv = bvs[0]; int fk = bks[0];
            #pragma unroll
            for (int i = 1; i < 8; i++)
                if (bvs[i] < fv || (bvs[i] == fv && bks[i] < fk)) { fv = bvs[i]; fk = bks[i]; }
            out[IDX0 + p] = (float)fk;
        }
        __syncthreads();
    }
}

// ---- K3: emit q + loss partials from final idx -----------------------------
__global__ void __launch_bounds__(256)
vq_emit(const float* __restrict__ z, const float* __restrict__ emb,
        float* __restrict__ out) {
    __shared__ float reds[8];
    const int p = blockIdx.x * 256 + threadIdx.x;
    const int b = p >> 12, hw = p & 4095;
    const int k = (int)out[IDX0 + p];
    const float4* er = reinterpret_cast<const float4*>(emb + (size_t)k * CC);
    const float* zp = z + (size_t)b * (CC * CHW) + hw;
    float* qp = out + (size_t)b * (CC * CHW) + hw;

    float sumsq = 0.f;
    #pragma unroll
    for (int i = 0; i < 16; i++) {
        float4 e4 = __ldg(er + i);
        float ev[4] = {e4.x, e4.y, e4.z, e4.w};
        #pragma unroll
        for (int j = 0; j < 4; j++) {
            int c = 4 * i + j;
            float zv = zp[c * CHW];
            float dd = __fsub_rn(ev[j], zv);
            sumsq = __fadd_rn(sumsq, __fmul_rn(dd, dd));
            qp[c * CHW] = __fadd_rn(zv, dd);          // fl(z + fl(e - z))
        }
    }
    #pragma unroll
    for (int o = 16; o; o >>= 1)
        sumsq += __shfl_xor_sync(0xffffffffu, sumsq, o);
    if ((threadIdx.x & 31) == 0) reds[threadIdx.x >> 5] = sumsq;
    __syncthreads();
    if (threadIdx.x == 0) {
        float s = 0.f;
        #pragma unroll
        for (int w = 0; w < 8; w++) s += reds[w];
        g_part[blockIdx.x] = s;
    }
}

// ---- K4: finalize losses (parallel), reset worklist ------------------------
__global__ void __launch_bounds__(256)
vq_fin(float* __restrict__ out) {
    __shared__ float reds[8];
    const int tid = threadIdx.x;
    float s = g_part[tid];
    #pragma unroll
    for (int o = 16; o; o >>= 1)
        s += __shfl_xor_sync(0xffffffffu, s, o);
    if ((tid & 31) == 0) reds[tid >> 5] = s;
    __syncthreads();
    if (tid == 0) {
        float t = 0.f;
        #pragma unroll
        for (int w = 0; w < 8; w++) t += reds[w];
        float loss = t * (1.0f / (float)Q_ELEMS);
        out[LOSS0] = loss;
        out[LOSS1] = loss;
        g_cnt = 0;
    }
}

extern "C" void kernel_launch(void* const* d_in, const int* in_sizes, int n_in,
                              void* d_out, int out_size) {
    const float* z   = (const float*)d_in[0];
    const float* emb = (const float*)d_in[1];
    float* out = (float*)d_out;

    cudaFuncSetAttribute(vq_mma, cudaFuncAttributeMaxDynamicSharedMemorySize, SMEM_SZ);
    vq_mma<<<NCTA, NTHR, SMEM_SZ>>>(z, emb, out);
    vq_exact<<<512, 256>>>(z, emb, out);
    vq_emit<<<NPIX / 256, 256>>>(z, emb, out);
    vq_fin<<<1, 256>>>(out);
}